// round 16
// baseline (speedup 1.0000x reference)
#include <cuda_runtime.h>

#define NB    32
#define NC    2
#define PP    262144             // H*W
#define QQ    65536              // pixel quads per sample
#define BINS  2048
#define ROWS  (NC * NB)          // 64 rows, row = cc*NB + n
#define HT    1024               // threads per block
#define NW    (HT / 32)
#define SPS   9                  // slices (blocks) per sample -> grid 288
#define GRID  (NB * SPS)
#define SEG   (BINS / HT)        // 2 bins per thread in the tail scan

// Scratch (static device globals, zero-initialized at load; reset each call)
__device__ unsigned int g_part[(size_t)NB * SPS * NC * BINS]; // per-slice partial hists
__device__ int          g_cnt[NB];            // per-sample arrival counters
__device__ int          g_done;               // sample-completion counter
__device__ float        g_wrow[ROWS];
__device__ unsigned int g_valid[ROWS];

// one histogram chunk (1024 quads), inlined into fully-unrolled loops
__device__ __forceinline__ void hist_chunk(
    int chunk, int tid, bool is32,
    const int* __restrict__ t32, const void* __restrict__ tgt, int n,
    const float* __restrict__ x0, const float* __restrict__ x1,
    unsigned int* __restrict__ sh) {
  const int p = (chunk * HT + tid) * 4;

  unsigned int mbits;
  if (is32) {
    int4 qd = __ldcs((const int4*)(t32 + (size_t)n * PP + p));
    mbits = (unsigned)(qd.x == 0) | ((unsigned)(qd.y == 0) << 1) |
            ((unsigned)(qd.z == 0) << 2) | ((unsigned)(qd.w == 0) << 3);
  } else {
    // int64 targets, values 0/1: low 32-bit word decides; odd words are 0.
    const int4* p64 = (const int4*)((const long long*)tgt + (size_t)n * PP + p);
    int4 qa = __ldcs(p64);
    int4 qb = __ldcs(p64 + 1);
    mbits = (unsigned)(qa.x == 0) | ((unsigned)(qa.z == 0) << 1) |
            ((unsigned)(qb.x == 0) << 2) | ((unsigned)(qb.z == 0) << 3);
  }
  float4 v0 = __ldcs((const float4*)(x0 + p));
  float4 v1 = __ldcs((const float4*)(x1 + p));
  float xs0[4] = {v0.x, v0.y, v0.z, v0.w};
  float xs1[4] = {v1.x, v1.y, v1.z, v1.w};

#pragma unroll
  for (int k = 0; k < 4; k++) {
    bool  m0 = (mbits >> k) & 1u;       // class-0 mask; class-1 mask = !m0
    float a0 = xs0[k], a1 = xs1[k];
    float d0 = m0 ? (1.0f - a0) : a0;   // |mask - x|
    float d1 = m0 ? a1 : (1.0f - a1);
    unsigned int b0 = min((unsigned int)(d0 * (float)BINS), (unsigned int)(BINS - 1));
    unsigned int b1 = min((unsigned int)(d1 * (float)BINS), (unsigned int)(BINS - 1));
    atomicAdd(&sh[b0],        m0 ? 0x10000u : 1u);
    atomicAdd(&sh[BINS + b1], m0 ? 1u : 0x10000u);
  }
}

__global__ void __launch_bounds__(HT, 2) k_all(const float* __restrict__ x,
                                               const void*  __restrict__ tgt,
                                               const float* __restrict__ cw,
                                               const float* __restrict__ tw,
                                               float* __restrict__ out) {
  __shared__ unsigned int       sh[2 * BINS];   // 16 KB hist
  __shared__ unsigned long long swarp[NW];
  __shared__ float              sred[NW];
  __shared__ int                sint[NW];
  __shared__ int                sflag, slast;

  const int bid  = blockIdx.x;
  const int tid  = threadIdx.x;
  const int lane = tid & 31;
  const int w    = tid >> 5;

  // block -> (sample n, slice j). 64 chunks of 1024 quads per sample:
  // slices 0..7 take 7 chunks, slice 8 takes 8  (8*7 + 8 = 64).
  // Heavy (8-chunk) slices are bids 0..31 so wave-1 placement puts them on
  // 32 DISTINCT SMs — worst SM carries 8+7=15 chunks instead of 8+8=16.
  int n, j;
  if (bid < NB) { n = bid;             j = 8; }
  else          { n = (bid - NB) >> 3; j = (bid - NB) & 7; }
  const int chunk0 = (j < 8) ? j * 7 : 56;

  for (int i = tid; i < 2 * BINS; i += HT) sh[i] = 0u;

  // Detect targets dtype: if int32, odd 32-bit words carry real data -> some
  // nonzero. If int64 (values 0/1), odd words are all zero. Doubles as barrier.
  const int* t32 = (const int*)tgt;
  int probe = t32[2 * tid + 1];
  bool is32 = __syncthreads_or(probe != 0);

  // ---------------- histogram phase: fully-unrolled compile-time loops ----
  const float* __restrict__ x0 = x + ((size_t)n * NC + 0) * PP;
  const float* __restrict__ x1 = x + ((size_t)n * NC + 1) * PP;
  if (j < 8) {
#pragma unroll
    for (int c = 0; c < 7; c++)
      hist_chunk(chunk0 + c, tid, is32, t32, tgt, n, x0, x1, sh);
  } else {
#pragma unroll
    for (int c = 0; c < 8; c++)
      hist_chunk(chunk0 + c, tid, is32, t32, tgt, n, x0, x1, sh);
  }
  __syncthreads();

  // flush: plain vectorized stores to this slice's private slot
  uint4* __restrict__ dst =
      (uint4*)(g_part + ((size_t)(n * SPS + j) * NC) * BINS);
  const uint4* __restrict__ src = (const uint4*)sh;
#pragma unroll
  for (int i = tid; i < (2 * BINS) / 4; i += HT) dst[i] = src[i];

  // ---------------- arrival: last slice of this sample runs the scan tail ----
  __threadfence();              // flush stores globally visible
  __syncthreads();
  if (tid == 0) {
    int old = atomicAdd(&g_cnt[n], 1);
    sflag = (old == SPS - 1);
  }
  __syncthreads();
  if (!sflag) return;
  __threadfence();              // acquire

  // ---------------- scan tail: both class rows of sample n ----------------
  for (int cc = 0; cc < NC; cc++) {
    const int r = cc * NB + n;
    // thread owns SEG=2 bins [g, g+1]; thread 0 owns the HIGHEST bins
    const int g = BINS - SEG - tid * SEG;

    unsigned int h1[SEG], htot[SEG];
#pragma unroll
    for (int jj = 0; jj < SEG; jj++) { h1[jj] = 0u; htot[jj] = 0u; }

#pragma unroll
    for (int bb = 0; bb < SPS; bb++) {
      uint2 v = __ldcg((const uint2*)(g_part +
                 ((size_t)(n * SPS + bb) * NC + cc) * BINS + g));
      unsigned int vv[2] = {v.x, v.y};
#pragma unroll
      for (int jj = 0; jj < SEG; jj++) {
        unsigned int one = vv[jj] >> 16;
        h1[jj]   += one;
        htot[jj] += one + (vv[jj] & 0xffffu);
      }
    }

    // npred from histogram:
    //  m=0 pixels (lo16): d=a, a>0.25 <=> bin >= BINS/4
    //  m=1 pixels (hi16): d=1-a, a>0.25 <=> d<0.75 <=> bin < 3*BINS/4
    int np = 0;
    unsigned int ss1 = 0, sst = 0;
#pragma unroll
    for (int jj = 0; jj < SEG; jj++) {
      ss1 += h1[jj];
      sst += htot[jj];
      int bin = g + jj;
      unsigned int lo = htot[jj] - h1[jj];
      if (bin >= BINS / 4)     np += (int)lo;
      if (bin < 3 * BINS / 4)  np += (int)h1[jj];
    }

    // inclusive block scan over packed (s1|st)
    unsigned long long mine = ((unsigned long long)ss1 << 32) | (unsigned long long)sst;
    unsigned long long inc = mine;
#pragma unroll
    for (int off = 1; off < 32; off <<= 1) {
      unsigned long long u = __shfl_up_sync(0xffffffffu, inc, off);
      if (lane >= off) inc += u;
    }
    if (lane == 31) swarp[w] = inc;
    __syncthreads();
    if (w == 0) {
      unsigned long long v = (lane < NW) ? swarp[lane] : 0ull;
#pragma unroll
      for (int off = 1; off < NW; off <<= 1) {
        unsigned long long u = __shfl_up_sync(0xffffffffu, v, off);
        if (lane >= off) v += u;
      }
      if (lane < NW) swarp[lane] = v;
    }
    __syncthreads();
    unsigned long long woff = (w == 0) ? 0ull : swarp[w - 1];
    unsigned long long tot  = swarp[NW - 1];
    unsigned long long excl = woff + inc - mine;

    const unsigned int gts = (unsigned int)(tot >> 32);
    unsigned int K1 = (unsigned int)(excl >> 32);
    unsigned int K  = (unsigned int)(excl & 0xffffffffull);

    float iou_prev = (K == 0)
        ? 0.0f
        : 1.0f - __fdividef((float)(gts - K1), (float)(gts + K - K1));

    float acc = 0.0f;
#pragma unroll
    for (int jj = SEG - 1; jj >= 0; jj--) {
      if (htot[jj]) {
        K1 += h1[jj];
        K  += htot[jj];
        float iou = 1.0f - __fdividef((float)(gts - K1), (float)(gts + K - K1));
        float d   = ((float)(g + jj) + 0.5f) * (1.0f / (float)BINS);
        acc += d * (iou - iou_prev);
        iou_prev = iou;
      }
    }

    // block reduce acc (float) and np (int) — fixed trees -> deterministic
#pragma unroll
    for (int off = 16; off; off >>= 1) {
      acc += __shfl_down_sync(0xffffffffu, acc, off);
      np  += __shfl_down_sync(0xffffffffu, np,  off);
    }
    if (lane == 0) { sred[w] = acc; sint[w] = np; }
    __syncthreads();
    if (tid == 0) {
      float per = 0.0f; int npt = 0;
#pragma unroll
      for (int i = 0; i < NW; i++) { per += sred[i]; npt += sint[i]; }
      float cwv   = cw[cc];
      bool  empty = (gts == 0) && (npt == 0);
      bool  valid = (cwv != 0.0f) && !empty;
      g_wrow[r]  = valid ? per * tw[n] * cwv : 0.0f;
      g_valid[r] = valid ? 1u : 0u;
    }
    __syncthreads();
  }

  // ---------------- completion: last sample-finisher does the final sum ----
  if (tid == 0) {
    g_cnt[n] = 0;                      // reset for next replay
    __threadfence();
    int old = atomicAdd(&g_done, 1);
    slast = (old == NB - 1);
  }
  __syncthreads();
  if (!slast) return;
  __threadfence();

  // parallel deterministic final reduction (64 lanes of warps 0-1)
  {
    float Wv = 0.0f, Vv = 0.0f;
    if (tid < ROWS) {
      Wv = __ldcg(&g_wrow[tid]);
      Vv = (float)__ldcg(&g_valid[tid]);
    }
    if (tid < 64) {
#pragma unroll
      for (int off = 16; off; off >>= 1) {
        Wv += __shfl_down_sync(0xffffffffu, Wv, off);
        Vv += __shfl_down_sync(0xffffffffu, Vv, off);
      }
      if (lane == 0) { sred[w] = Wv; ((float*)swarp)[w] = Vv; }
    }
    __syncthreads();
    if (tid == 0) {
      float W = sred[0] + sred[1];
      float V = ((float*)swarp)[0] + ((float*)swarp)[1];
      out[0] = W / (float)NB / V;
      g_done = 0;                      // reset for next replay
    }
  }
}

// ---------------------------------------------------------------- launch
extern "C" void kernel_launch(void* const* d_in, const int* in_sizes, int n_in,
                              void* d_out, int out_size) {
  const float* x   = (const float*)d_in[0];
  const void*  tgt = d_in[1];
  const float* cw  = (const float*)d_in[2];
  const float* tw  = (const float*)d_in[3];
  float* out = (float*)d_out;

  k_all<<<GRID, HT>>>(x, tgt, cw, tw, out);
}

// round 17
// speedup vs baseline: 1.0094x; 1.0094x over previous
#include <cuda_runtime.h>

#define NB    32
#define NC    2
#define PP    262144             // H*W
#define QQ    65536              // pixel quads per sample
#define BINS  2048
#define ROWS  (NC * NB)          // 64 rows, row = cc*NB + n
#define HT    1024               // threads per block
#define NW    (HT / 32)
#define SPS   9                  // slices (blocks) per sample -> grid 288
#define GRID  (NB * SPS)
#define SEG   (BINS / HT)        // 2 bins per thread in the tail scan

// Scratch (static device globals, zero-initialized at load; reset each call)
__device__ unsigned int g_part[(size_t)NB * SPS * NC * BINS]; // per-slice partial hists
__device__ int          g_cnt[NB];            // per-sample arrival counters
__device__ int          g_done;               // sample-completion counter
__device__ float        g_wrow[ROWS];
__device__ unsigned int g_valid[ROWS];

// one histogram chunk (1024 quads), inlined into fully-unrolled loops.
// sh layout: [0,B)=c0/m0  [B,2B)=c0/m1  [2B,3B)=c1/m0  [3B,4B)=c1/m1
__device__ __forceinline__ void hist_chunk(
    int chunk, int tid, bool is32,
    const int* __restrict__ t32, const void* __restrict__ tgt, int n,
    const float* __restrict__ x0, const float* __restrict__ x1,
    unsigned int* __restrict__ sh) {
  const int p = (chunk * HT + tid) * 4;

  unsigned int mbits;
  if (is32) {
    int4 qd = __ldcs((const int4*)(t32 + (size_t)n * PP + p));
    mbits = (unsigned)(qd.x == 0) | ((unsigned)(qd.y == 0) << 1) |
            ((unsigned)(qd.z == 0) << 2) | ((unsigned)(qd.w == 0) << 3);
  } else {
    // int64 targets, values 0/1: low 32-bit word decides; odd words are 0.
    const int4* p64 = (const int4*)((const long long*)tgt + (size_t)n * PP + p);
    int4 qa = __ldcs(p64);
    int4 qb = __ldcs(p64 + 1);
    mbits = (unsigned)(qa.x == 0) | ((unsigned)(qa.z == 0) << 1) |
            ((unsigned)(qb.x == 0) << 2) | ((unsigned)(qb.z == 0) << 3);
  }
  float4 v0 = __ldcs((const float4*)(x0 + p));
  float4 v1 = __ldcs((const float4*)(x1 + p));
  float xs0[4] = {v0.x, v0.y, v0.z, v0.w};
  float xs1[4] = {v1.x, v1.y, v1.z, v1.w};

#pragma unroll
  for (int k = 0; k < 4; k++) {
    unsigned int m0 = (mbits >> k) & 1u;    // class-0 mask; class-1 mask = !m0
    float a0 = xs0[k], a1 = xs1[k];
    float d0 = m0 ? (1.0f - a0) : a0;       // |mask - x|
    float d1 = m0 ? a1 : (1.0f - a1);
    unsigned int b0 = min((unsigned int)(d0 * (float)BINS), (unsigned int)(BINS - 1));
    unsigned int b1 = min((unsigned int)(d1 * (float)BINS), (unsigned int)(BINS - 1));
    // fold mask into index: collisions need same bin AND same mask
    atomicAdd(&sh[b0 + (m0 << 11)], 1u);
    atomicAdd(&sh[2 * BINS + b1 + ((m0 ^ 1u) << 11)], 1u);
  }
}

__global__ void __launch_bounds__(HT, 2) k_all(const float* __restrict__ x,
                                               const void*  __restrict__ tgt,
                                               const float* __restrict__ cw,
                                               const float* __restrict__ tw,
                                               float* __restrict__ out) {
  __shared__ unsigned int       sh[4 * BINS];   // 32 KB: 2 classes x 2 mask halves
  __shared__ unsigned long long swarp[NW];
  __shared__ float              sred[NW];
  __shared__ int                sint[NW];
  __shared__ int                sflag, slast;

  const int bid  = blockIdx.x;
  const int tid  = threadIdx.x;
  const int lane = tid & 31;
  const int w    = tid >> 5;

  // block -> (sample n, slice j). 64 chunks of 1024 quads per sample:
  // heavy (8-chunk) slices are bids 0..31 (distinct SMs in wave-1).
  int n, j;
  if (bid < NB) { n = bid;             j = 8; }
  else          { n = (bid - NB) >> 3; j = (bid - NB) & 7; }
  const int chunk0 = (j < 8) ? j * 7 : 56;

  for (int i = tid; i < 4 * BINS; i += HT) sh[i] = 0u;

  // Detect targets dtype: if int32, odd 32-bit words carry real data -> some
  // nonzero. If int64 (values 0/1), odd words are all zero. Doubles as barrier.
  const int* t32 = (const int*)tgt;
  int probe = t32[2 * tid + 1];
  bool is32 = __syncthreads_or(probe != 0);

  // ---------------- histogram phase: fully-unrolled compile-time loops ----
  const float* __restrict__ x0 = x + ((size_t)n * NC + 0) * PP;
  const float* __restrict__ x1 = x + ((size_t)n * NC + 1) * PP;
  if (j < 8) {
#pragma unroll
    for (int c = 0; c < 7; c++)
      hist_chunk(chunk0 + c, tid, is32, t32, tgt, n, x0, x1, sh);
  } else {
#pragma unroll
    for (int c = 0; c < 8; c++)
      hist_chunk(chunk0 + c, tid, is32, t32, tgt, n, x0, x1, sh);
  }
  __syncthreads();

  // flush: pack mask-halves into (m1<<16)|m0 — g_part format identical to before
  {
    unsigned int* __restrict__ dst =
        g_part + ((size_t)(n * SPS + j) * NC) * BINS;
#pragma unroll
    for (int i = tid; i < BINS; i += HT) {
      dst[i]        = (sh[BINS + i]     << 16) | sh[i];             // class 0
      dst[BINS + i] = (sh[3 * BINS + i] << 16) | sh[2 * BINS + i];  // class 1
    }
  }

  // ---------------- arrival: last slice of this sample runs the scan tail ----
  __threadfence();              // flush stores globally visible
  __syncthreads();
  if (tid == 0) {
    int old = atomicAdd(&g_cnt[n], 1);
    sflag = (old == SPS - 1);
  }
  __syncthreads();
  if (!sflag) return;
  __threadfence();              // acquire

  // ---------------- scan tail: both class rows of sample n ----------------
  for (int cc = 0; cc < NC; cc++) {
    const int r = cc * NB + n;
    // thread owns SEG=2 bins [g, g+1]; thread 0 owns the HIGHEST bins
    const int g = BINS - SEG - tid * SEG;

    unsigned int h1[SEG], htot[SEG];
#pragma unroll
    for (int jj = 0; jj < SEG; jj++) { h1[jj] = 0u; htot[jj] = 0u; }

#pragma unroll
    for (int bb = 0; bb < SPS; bb++) {
      uint2 v = __ldcg((const uint2*)(g_part +
                 ((size_t)(n * SPS + bb) * NC + cc) * BINS + g));
      unsigned int vv[2] = {v.x, v.y};
#pragma unroll
      for (int jj = 0; jj < SEG; jj++) {
        unsigned int one = vv[jj] >> 16;
        h1[jj]   += one;
        htot[jj] += one + (vv[jj] & 0xffffu);
      }
    }

    // npred from histogram:
    //  m=0 pixels (lo16): d=a, a>0.25 <=> bin >= BINS/4
    //  m=1 pixels (hi16): d=1-a, a>0.25 <=> d<0.75 <=> bin < 3*BINS/4
    int np = 0;
    unsigned int ss1 = 0, sst = 0;
#pragma unroll
    for (int jj = 0; jj < SEG; jj++) {
      ss1 += h1[jj];
      sst += htot[jj];
      int bin = g + jj;
      unsigned int lo = htot[jj] - h1[jj];
      if (bin >= BINS / 4)     np += (int)lo;
      if (bin < 3 * BINS / 4)  np += (int)h1[jj];
    }

    // inclusive block scan over packed (s1|st)
    unsigned long long mine = ((unsigned long long)ss1 << 32) | (unsigned long long)sst;
    unsigned long long inc = mine;
#pragma unroll
    for (int off = 1; off < 32; off <<= 1) {
      unsigned long long u = __shfl_up_sync(0xffffffffu, inc, off);
      if (lane >= off) inc += u;
    }
    if (lane == 31) swarp[w] = inc;
    __syncthreads();
    if (w == 0) {
      unsigned long long v = (lane < NW) ? swarp[lane] : 0ull;
#pragma unroll
      for (int off = 1; off < NW; off <<= 1) {
        unsigned long long u = __shfl_up_sync(0xffffffffu, v, off);
        if (lane >= off) v += u;
      }
      if (lane < NW) swarp[lane] = v;
    }
    __syncthreads();
    unsigned long long woff = (w == 0) ? 0ull : swarp[w - 1];
    unsigned long long tot  = swarp[NW - 1];
    unsigned long long excl = woff + inc - mine;

    const unsigned int gts = (unsigned int)(tot >> 32);
    unsigned int K1 = (unsigned int)(excl >> 32);
    unsigned int K  = (unsigned int)(excl & 0xffffffffull);

    float iou_prev = (K == 0)
        ? 0.0f
        : 1.0f - __fdividef((float)(gts - K1), (float)(gts + K - K1));

    float acc = 0.0f;
#pragma unroll
    for (int jj = SEG - 1; jj >= 0; jj--) {
      if (htot[jj]) {
        K1 += h1[jj];
        K  += htot[jj];
        float iou = 1.0f - __fdividef((float)(gts - K1), (float)(gts + K - K1));
        float d   = ((float)(g + jj) + 0.5f) * (1.0f / (float)BINS);
        acc += d * (iou - iou_prev);
        iou_prev = iou;
      }
    }

    // block reduce acc (float) and np (int) — fixed trees -> deterministic
#pragma unroll
    for (int off = 16; off; off >>= 1) {
      acc += __shfl_down_sync(0xffffffffu, acc, off);
      np  += __shfl_down_sync(0xffffffffu, np,  off);
    }
    if (lane == 0) { sred[w] = acc; sint[w] = np; }
    __syncthreads();
    if (tid == 0) {
      float per = 0.0f; int npt = 0;
#pragma unroll
      for (int i = 0; i < NW; i++) { per += sred[i]; npt += sint[i]; }
      float cwv   = cw[cc];
      bool  empty = (gts == 0) && (npt == 0);
      bool  valid = (cwv != 0.0f) && !empty;
      g_wrow[r]  = valid ? per * tw[n] * cwv : 0.0f;
      g_valid[r] = valid ? 1u : 0u;
    }
    __syncthreads();
  }

  // ---------------- completion: last sample-finisher does the final sum ----
  if (tid == 0) {
    g_cnt[n] = 0;                      // reset for next replay
    __threadfence();
    int old = atomicAdd(&g_done, 1);
    slast = (old == NB - 1);
  }
  __syncthreads();
  if (!slast) return;
  __threadfence();

  // parallel deterministic final reduction (64 lanes of warps 0-1)
  {
    float Wv = 0.0f, Vv = 0.0f;
    if (tid < ROWS) {
      Wv = __ldcg(&g_wrow[tid]);
      Vv = (float)__ldcg(&g_valid[tid]);
    }
    if (tid < 64) {
#pragma unroll
      for (int off = 16; off; off >>= 1) {
        Wv += __shfl_down_sync(0xffffffffu, Wv, off);
        Vv += __shfl_down_sync(0xffffffffu, Vv, off);
      }
      if (lane == 0) { sred[w] = Wv; ((float*)swarp)[w] = Vv; }
    }
    __syncthreads();
    if (tid == 0) {
      float W = sred[0] + sred[1];
      float V = ((float*)swarp)[0] + ((float*)swarp)[1];
      out[0] = W / (float)NB / V;
      g_done = 0;                      // reset for next replay
    }
  }
}

// ---------------------------------------------------------------- launch
extern "C" void kernel_launch(void* const* d_in, const int* in_sizes, int n_in,
                              void* d_out, int out_size) {
  const float* x   = (const float*)d_in[0];
  const void*  tgt = d_in[1];
  const float* cw  = (const float*)d_in[2];
  const float* tw  = (const float*)d_in[3];
  float* out = (float*)d_out;

  k_all<<<GRID, HT>>>(x, tgt, cw, tw, out);
}